// round 13
// baseline (speedup 1.0000x reference)
#include <cuda_runtime.h>
#include <cuda_bf16.h>
#include <cstdint>

// Problem constants
#define T_TYPES 27
#define N_NODES 16384
#define B_BATCH 256
#define IN_DIM  300
#define HID     128
#define OUT_DIM 64
#define TILE_B  8
#define N_TILES (B_BATCH / TILE_B)     // 32
#define ROW_BYTES 1200                 // 300 floats
#define CHUNK_ROWS 7
#define CHUNK_BYTES (CHUNK_ROWS * ROW_BYTES)   // 8400
#define NSTAGE 3
#define ROW_ULL 150                    // 300 floats = 150 f32x2

__device__ int g_bounds[T_TYPES * (B_BATCH + 1)];

typedef unsigned long long ull;

__device__ __forceinline__ ull fma2(ull a, ull b, ull c) {
    ull d;
    asm("fma.rn.f32x2 %0, %1, %2, %3;" : "=l"(d) : "l"(a), "l"(b), "l"(c));
    return d;
}
__device__ __forceinline__ ull add2(ull a, ull b) {
    ull d;
    asm("add.rn.f32x2 %0, %1, %2;" : "=l"(d) : "l"(a), "l"(b));
    return d;
}
__device__ __forceinline__ ull mul2(ull a, ull b) {
    ull d;
    asm("mul.rn.f32x2 %0, %1, %2;" : "=l"(d) : "l"(a), "l"(b));
    return d;
}
__device__ __forceinline__ ull pack2(float x) {
    ull d; asm("mov.b64 %0, {%1, %1};" : "=l"(d) : "f"(x)); return d;
}
__device__ __forceinline__ ull packab(float a, float b) {
    ull d; asm("mov.b64 %0, {%1, %2};" : "=l"(d) : "f"(a), "f"(b)); return d;
}
__device__ __forceinline__ void unpack2(ull v, float& lo, float& hi) {
    asm("mov.b64 {%0, %1}, %2;" : "=f"(lo), "=f"(hi) : "l"(v));
}
__device__ __forceinline__ ull relu2(ull v) {
    float lo, hi; unpack2(v, lo, hi);
    return packab(fmaxf(lo, 0.f), fmaxf(hi, 0.f));
}

__device__ __forceinline__ uint32_t s2u(const void* p) {
    uint32_t a;
    asm("{ .reg .u64 t; cvta.to.shared.u64 t, %1; cvt.u32.u64 %0, t; }"
        : "=r"(a) : "l"(p));
    return a;
}
__device__ __forceinline__ void mbar_init(uint32_t m, uint32_t cnt) {
    asm volatile("mbarrier.init.shared.b64 [%0], %1;" :: "r"(m), "r"(cnt) : "memory");
}
__device__ __forceinline__ void mbar_expect_tx(uint32_t m, uint32_t bytes) {
    asm volatile("mbarrier.arrive.expect_tx.shared.b64 _, [%0], %1;"
                 :: "r"(m), "r"(bytes) : "memory");
}
__device__ __forceinline__ void bulk_g2s(uint32_t dst, const void* src,
                                         uint32_t bytes, uint32_t m) {
    asm volatile(
        "cp.async.bulk.shared::cta.global.mbarrier::complete_tx::bytes "
        "[%0], [%1], %2, [%3];"
        :: "r"(dst), "l"(src), "r"(bytes), "r"(m) : "memory");
}
__device__ __forceinline__ void mbar_wait(uint32_t m, int parity) {
    asm volatile(
        "{\n\t"
        ".reg .pred P;\n\t"
        "WAIT_%=:\n\t"
        "mbarrier.try_wait.parity.acquire.cta.shared::cta.b64 P, [%0], %1;\n\t"
        "@!P bra WAIT_%=;\n\t"
        "}" :: "r"(m), "r"(parity) : "memory");
}

// ---------------------------------------------------------------------------
// Kernel 0: segment bounds via histogram + scan. grid=27, block=256.
// ---------------------------------------------------------------------------
__global__ void bounds_kernel(const int* __restrict__ seg) {
    const int t = blockIdx.x;
    const int tid = threadIdx.x;
    __shared__ int hist[B_BATCH];

    hist[tid] = 0;
    __syncthreads();
    const int* s = seg + (size_t)t * N_NODES;
    for (int i = tid; i < N_NODES; i += B_BATCH)
        atomicAdd(&hist[s[i]], 1);
    __syncthreads();

    for (int off = 1; off < B_BATCH; off <<= 1) {
        int u = (tid >= off) ? hist[tid - off] : 0;
        __syncthreads();
        hist[tid] += u;
        __syncthreads();
    }
    if (tid == 0) g_bounds[t * (B_BATCH + 1)] = 0;
    g_bounds[t * (B_BATCH + 1) + tid + 1] = hist[tid];
}

// ---------------------------------------------------------------------------
// Fused kernel: grid=(32, 27) = 864 blocks (single wave @6/SM), 128 threads.
// Phase 1: 3-stage cp.async.bulk ring (2 chunks in flight during consume);
//          per-thread f32x2 column accumulators, in-order segment flushes.
// Phase 2: 2-layer MLP from smem (ht overlays the dma ring).
// ---------------------------------------------------------------------------
__global__ __launch_bounds__(128, 6)
void fused_kernel(const float* __restrict__ feat,
                  const float* __restrict__ W1,
                  const float* __restrict__ b1,
                  const float* __restrict__ W2,
                  const float* __restrict__ b2,
                  float* __restrict__ out) {
    const int t   = blockIdx.y;
    const int b0  = blockIdx.x * TILE_B;
    const int tid = threadIdx.x;

    __shared__ __align__(128) char  s_dma[NSTAGE * CHUNK_BYTES];  // 25200 B
    __shared__ __align__(16)  float s_pool[TILE_B * IN_DIM];      //  9600 B [b][k]
    __shared__ __align__(8)   ull   s_mbar[NSTAGE];
    __shared__ int s_bnd[TILE_B + 1];

    if (tid < TILE_B + 1)
        s_bnd[tid] = g_bounds[t * (B_BATCH + 1) + b0 + tid];
    if (tid == 0) {
        #pragma unroll
        for (int s = 0; s < NSTAGE; ++s) mbar_init(s2u(&s_mbar[s]), 1);
    }
    __syncthreads();

    const int lo0 = s_bnd[0];
    const int total_rows = s_bnd[TILE_B] - lo0;
    const uint32_t total_bytes = (uint32_t)total_rows * ROW_BYTES;
    const int nch = (int)((total_bytes + CHUNK_BYTES - 1) / CHUNK_BYTES);

    const uint32_t dma_u32 = s2u(s_dma);
    uint32_t mb[NSTAGE];
    #pragma unroll
    for (int s = 0; s < NSTAGE; ++s) mb[s] = s2u(&s_mbar[s]);
    const char* gsrc = (const char*)(feat + ((size_t)t * N_NODES + lo0) * IN_DIM);

    // ---------------- Phase 1: deep TMA-bulk pipeline + segmented reduce ------
    ull acc0 = 0ull, acc1 = 0ull;
    const bool hasB = tid < (ROW_ULL - 128);   // tid < 22 owns a 2nd column
    int cur = 0;
    int cur_start = 0;
    int cur_end = s_bnd[1] - lo0;
    int ph[NSTAGE];
    #pragma unroll
    for (int s = 0; s < NSTAGE; ++s) ph[s] = 0;

    #define FLUSH() do {                                                        \
        const int cseg = cur;                                                   \
        const int ccnt = cur_end - cur_start;                                   \
        ull inv2 = pack2(1.0f / (float)max(ccnt, 1));                           \
        *(ull*)&s_pool[cseg * IN_DIM + 2 * tid] = mul2(acc0, inv2);             \
        if (hasB)                                                               \
            *(ull*)&s_pool[cseg * IN_DIM + 2 * (128 + tid)] = mul2(acc1, inv2); \
        acc0 = 0ull; acc1 = 0ull;                                               \
        cur++;                                                                  \
        cur_start = cur_end;                                                    \
        cur_end = (cur < TILE_B) ? (s_bnd[cur + 1] - lo0) : 0x7fffffff;         \
    } while (0)

    // prologue: fill the ring
    if (tid == 0) {
        #pragma unroll
        for (int s = 0; s < NSTAGE; ++s) {
            if (s < nch) {
                uint32_t off = (uint32_t)s * CHUNK_BYTES;
                uint32_t bytes = min((uint32_t)CHUNK_BYTES, total_bytes - off);
                mbar_expect_tx(mb[s], bytes);
                bulk_g2s(dma_u32 + s * CHUNK_BYTES, gsrc + off, bytes, mb[s]);
            }
        }
    }

    for (int c = 0; c < nch; ++c) {
        const int st = c % NSTAGE;
        mbar_wait(mb[st], ph[st]);
        ph[st] ^= 1;

        const char* buf = s_dma + st * CHUNK_BYTES;
        const int r0 = c * CHUNK_ROWS;
        const int rows = min(CHUNK_ROWS, total_rows - r0);
        #pragma unroll
        for (int r = 0; r < CHUNK_ROWS; ++r) {
            if (r >= rows) break;
            const int gr = r0 + r;
            while (gr == cur_end) FLUSH();       // uniform across threads
            acc0 = add2(acc0, *(const ull*)(buf + r * ROW_BYTES + tid * 8));
            if (hasB)
                acc1 = add2(acc1, *(const ull*)(buf + r * ROW_BYTES + (128 + tid) * 8));
        }
        __syncthreads();   // all threads done reading buf st before reissue

        if (tid == 0 && c + NSTAGE < nch) {
            uint32_t off = (uint32_t)(c + NSTAGE) * CHUNK_BYTES;
            uint32_t bytes = min((uint32_t)CHUNK_BYTES, total_bytes - off);
            mbar_expect_tx(mb[st], bytes);
            bulk_g2s(dma_u32 + st * CHUNK_BYTES, gsrc + off, bytes, mb[st]);
        }
    }
    while (cur < TILE_B) FLUSH();                // tail (incl. trailing empties)
    #undef FLUSH
    __syncthreads();

    // ht overlays the dma ring (streaming complete)
    float* s_ht = (float*)s_dma;   // [b][j], 4096 B

    // ---------------- Phase 2: GEMM1 (j-packed f32x2) ----------------
    const int jq = tid & 31;
    const int p  = tid >> 5;

    ull a00, a01, a10, a11;
    {
        ulonglong2 bi = *(const ulonglong2*)&b1[t * HID + 4 * jq];
        a00 = bi.x; a01 = bi.x; a10 = bi.y; a11 = bi.y;
    }
    {
        const float* w1p = W1 + (size_t)t * IN_DIM * HID + 4 * jq;
        const float* r0 = &s_pool[(2 * p) * IN_DIM];
        const float* r1 = &s_pool[(2 * p + 1) * IN_DIM];

        ulonglong2 wc[4], wn[4];
        #pragma unroll
        for (int q = 0; q < 4; ++q)
            wc[q] = *(const ulonglong2*)(w1p + q * HID);

        for (int kg = 0; kg < IN_DIM / 4; ++kg) {
            const int kb = kg * 4;
            if (kg + 1 < IN_DIM / 4) {
                const float* wq = w1p + (kb + 4) * HID;
                #pragma unroll
                for (int q = 0; q < 4; ++q)
                    wn[q] = *(const ulonglong2*)(wq + q * HID);
            }
            #pragma unroll
            for (int q = 0; q < 4; ++q) {
                ull sv0 = pack2(r0[kb + q]);
                ull sv1 = pack2(r1[kb + q]);
                a00 = fma2(wc[q].x, sv0, a00);
                a01 = fma2(wc[q].x, sv1, a01);
                a10 = fma2(wc[q].y, sv0, a10);
                a11 = fma2(wc[q].y, sv1, a11);
            }
            #pragma unroll
            for (int q = 0; q < 4; ++q) wc[q] = wn[q];
        }
    }

    *(ulonglong2*)&s_ht[(2 * p) * HID + 4 * jq] =
        make_ulonglong2(relu2(a00), relu2(a10));
    *(ulonglong2*)&s_ht[(2 * p + 1) * HID + 4 * jq] =
        make_ulonglong2(relu2(a01), relu2(a11));
    __syncthreads();

    // ---------------- Phase 3: GEMM2 (packed over j-pairs) ----------------
    const int o  = tid & 63;
    const int rh = tid >> 6;               // rows rh*4 .. rh*4+3

    ull c0 = 0ull, c1 = 0ull, c2 = 0ull, c3 = 0ull;
    {
        const float* w2p = W2 + (size_t)t * HID * OUT_DIM + o;
        float wlo[4], whi[4], nlo[4], nhi[4];
        #pragma unroll
        for (int q = 0; q < 4; ++q) {
            wlo[q] = w2p[(2 * q) * OUT_DIM];
            whi[q] = w2p[(2 * q + 1) * OUT_DIM];
        }
        for (int jg = 0; jg < 16; ++jg) {      // 64 j-pairs / 4
            const int jb = jg * 4;
            if (jg + 1 < 16) {
                #pragma unroll
                for (int q = 0; q < 4; ++q) {
                    nlo[q] = w2p[(2 * (jb + 4 + q)) * OUT_DIM];
                    nhi[q] = w2p[(2 * (jb + 4 + q) + 1) * OUT_DIM];
                }
            }
            #pragma unroll
            for (int q = 0; q < 4; ++q) {
                const int jp = jb + q;
                ull wp = packab(wlo[q], whi[q]);
                c0 = fma2(wp, *(const ull*)&s_ht[(rh * 4 + 0) * HID + 2 * jp], c0);
                c1 = fma2(wp, *(const ull*)&s_ht[(rh * 4 + 1) * HID + 2 * jp], c1);
                c2 = fma2(wp, *(const ull*)&s_ht[(rh * 4 + 2) * HID + 2 * jp], c2);
                c3 = fma2(wp, *(const ull*)&s_ht[(rh * 4 + 3) * HID + 2 * jp], c3);
            }
            #pragma unroll
            for (int q = 0; q < 4; ++q) { wlo[q] = nlo[q]; whi[q] = nhi[q]; }
        }
    }

    {
        const float bo = b2[t * OUT_DIM + o];
        float lo2, hi2;
        unpack2(c0, lo2, hi2);
        out[((size_t)(b0 + rh * 4 + 0) * T_TYPES + t) * OUT_DIM + o] = lo2 + hi2 + bo;
        unpack2(c1, lo2, hi2);
        out[((size_t)(b0 + rh * 4 + 1) * T_TYPES + t) * OUT_DIM + o] = lo2 + hi2 + bo;
        unpack2(c2, lo2, hi2);
        out[((size_t)(b0 + rh * 4 + 2) * T_TYPES + t) * OUT_DIM + o] = lo2 + hi2 + bo;
        unpack2(c3, lo2, hi2);
        out[((size_t)(b0 + rh * 4 + 3) * T_TYPES + t) * OUT_DIM + o] = lo2 + hi2 + bo;
    }
}

// ---------------------------------------------------------------------------
extern "C" void kernel_launch(void* const* d_in, const int* in_sizes, int n_in,
                              void* d_out, int out_size) {
    const float* feat = (const float*)d_in[0];
    const int*   seg  = (const int*)d_in[1];
    const float* W1   = (const float*)d_in[2];
    const float* b1   = (const float*)d_in[3];
    const float* W2   = (const float*)d_in[4];
    const float* b2   = (const float*)d_in[5];
    float* out = (float*)d_out;

    bounds_kernel<<<T_TYPES, B_BATCH>>>(seg);

    dim3 grid(N_TILES, T_TYPES);
    fused_kernel<<<grid, 128>>>(feat, W1, b1, W2, b2, out);
}

// round 14
// speedup vs baseline: 1.2783x; 1.2783x over previous
#include <cuda_runtime.h>
#include <cuda_bf16.h>
#include <cstdint>

// Problem constants
#define T_TYPES 27
#define N_NODES 16384
#define B_BATCH 256
#define IN_DIM  300
#define HID     128
#define OUT_DIM 64
#define TILE_B  8
#define N_TILES (B_BATCH / TILE_B)     // 32
#define ROW_BYTES 1200                 // 300 floats
#define CHUNK_ROWS 6
#define CHUNK_BYTES (CHUNK_ROWS * ROW_BYTES)   // 7200
#define NSTAGE 3
#define ROW_ULL 150                    // 300 floats = 150 f32x2

__device__ int g_bounds[T_TYPES * (B_BATCH + 1)];

typedef unsigned long long ull;

__device__ __forceinline__ ull fma2(ull a, ull b, ull c) {
    ull d;
    asm("fma.rn.f32x2 %0, %1, %2, %3;" : "=l"(d) : "l"(a), "l"(b), "l"(c));
    return d;
}
__device__ __forceinline__ ull add2(ull a, ull b) {
    ull d;
    asm("add.rn.f32x2 %0, %1, %2;" : "=l"(d) : "l"(a), "l"(b));
    return d;
}
__device__ __forceinline__ ull mul2(ull a, ull b) {
    ull d;
    asm("mul.rn.f32x2 %0, %1, %2;" : "=l"(d) : "l"(a), "l"(b));
    return d;
}
__device__ __forceinline__ ull pack2(float x) {
    ull d; asm("mov.b64 %0, {%1, %1};" : "=l"(d) : "f"(x)); return d;
}
__device__ __forceinline__ ull packab(float a, float b) {
    ull d; asm("mov.b64 %0, {%1, %2};" : "=l"(d) : "f"(a), "f"(b)); return d;
}
__device__ __forceinline__ void unpack2(ull v, float& lo, float& hi) {
    asm("mov.b64 {%0, %1}, %2;" : "=f"(lo), "=f"(hi) : "l"(v));
}
__device__ __forceinline__ ull relu2(ull v) {
    float lo, hi; unpack2(v, lo, hi);
    return packab(fmaxf(lo, 0.f), fmaxf(hi, 0.f));
}

__device__ __forceinline__ uint32_t s2u(const void* p) {
    uint32_t a;
    asm("{ .reg .u64 t; cvta.to.shared.u64 t, %1; cvt.u32.u64 %0, t; }"
        : "=r"(a) : "l"(p));
    return a;
}
__device__ __forceinline__ void mbar_init(uint32_t m, uint32_t cnt) {
    asm volatile("mbarrier.init.shared.b64 [%0], %1;" :: "r"(m), "r"(cnt) : "memory");
}
__device__ __forceinline__ void mbar_expect_tx(uint32_t m, uint32_t bytes) {
    asm volatile("mbarrier.arrive.expect_tx.shared.b64 _, [%0], %1;"
                 :: "r"(m), "r"(bytes) : "memory");
}
__device__ __forceinline__ void bulk_g2s(uint32_t dst, const void* src,
                                         uint32_t bytes, uint32_t m) {
    asm volatile(
        "cp.async.bulk.shared::cta.global.mbarrier::complete_tx::bytes "
        "[%0], [%1], %2, [%3];"
        :: "r"(dst), "l"(src), "r"(bytes), "r"(m) : "memory");
}
__device__ __forceinline__ void mbar_wait(uint32_t m, int parity) {
    asm volatile(
        "{\n\t"
        ".reg .pred P;\n\t"
        "WAIT_%=:\n\t"
        "mbarrier.try_wait.parity.acquire.cta.shared::cta.b64 P, [%0], %1;\n\t"
        "@!P bra WAIT_%=;\n\t"
        "}" :: "r"(m), "r"(parity) : "memory");
}

// ---------------------------------------------------------------------------
// Kernel 0: segment bounds via histogram + scan. grid=27, block=256.
// ---------------------------------------------------------------------------
__global__ void bounds_kernel(const int* __restrict__ seg) {
    const int t = blockIdx.x;
    const int tid = threadIdx.x;
    __shared__ int hist[B_BATCH];

    hist[tid] = 0;
    __syncthreads();
    const int* s = seg + (size_t)t * N_NODES;
    for (int i = tid; i < N_NODES; i += B_BATCH)
        atomicAdd(&hist[s[i]], 1);
    __syncthreads();

    for (int off = 1; off < B_BATCH; off <<= 1) {
        int u = (tid >= off) ? hist[tid - off] : 0;
        __syncthreads();
        hist[tid] += u;
        __syncthreads();
    }
    if (tid == 0) g_bounds[t * (B_BATCH + 1)] = 0;
    g_bounds[t * (B_BATCH + 1) + tid + 1] = hist[tid];
}

// ---------------------------------------------------------------------------
// Fused kernel: grid=(32, 27) = 864 blocks (single wave @6/SM), 128 threads.
// Phase 1: 3-stage cp.async.bulk ring with COMPILE-TIME stage indices
//          (2 chunks in flight during each consume).
// Phase 2: 2-layer MLP from smem (ht overlays the dma ring).
// ---------------------------------------------------------------------------
__global__ __launch_bounds__(128, 6)
void fused_kernel(const float* __restrict__ feat,
                  const float* __restrict__ W1,
                  const float* __restrict__ b1,
                  const float* __restrict__ W2,
                  const float* __restrict__ b2,
                  float* __restrict__ out) {
    const int t   = blockIdx.y;
    const int b0  = blockIdx.x * TILE_B;
    const int tid = threadIdx.x;

    __shared__ __align__(128) char  s_dma[NSTAGE * CHUNK_BYTES];  // 21600 B
    __shared__ __align__(16)  float s_pool[TILE_B * IN_DIM];      //  9600 B [b][k]
    __shared__ __align__(8)   ull   s_mbar[NSTAGE];
    __shared__ int s_bnd[TILE_B + 1];

    if (tid < TILE_B + 1)
        s_bnd[tid] = g_bounds[t * (B_BATCH + 1) + b0 + tid];
    if (tid == 0) {
        mbar_init(s2u(&s_mbar[0]), 1);
        mbar_init(s2u(&s_mbar[1]), 1);
        mbar_init(s2u(&s_mbar[2]), 1);
    }
    __syncthreads();

    const int lo0 = s_bnd[0];
    const int total_rows = s_bnd[TILE_B] - lo0;
    const uint32_t total_bytes = (uint32_t)total_rows * ROW_BYTES;
    const int nch = (int)((total_bytes + CHUNK_BYTES - 1) / CHUNK_BYTES);

    const uint32_t dma_u32 = s2u(s_dma);
    const uint32_t mb0 = s2u(&s_mbar[0]);
    const uint32_t mb1 = s2u(&s_mbar[1]);
    const uint32_t mb2 = s2u(&s_mbar[2]);
    const char* gsrc = (const char*)(feat + ((size_t)t * N_NODES + lo0) * IN_DIM);

    // ---------------- Phase 1: deep TMA-bulk pipeline + segmented reduce ------
    ull acc0 = 0ull, acc1 = 0ull;
    const bool hasB = tid < (ROW_ULL - 128);   // tid < 22 owns a 2nd column
    int cur = 0;
    int cur_start = 0;
    int cur_end = s_bnd[1] - lo0;
    int ph0 = 0, ph1 = 0, ph2 = 0;             // scalar phase bits

    #define FLUSH() do {                                                        \
        const int cseg = cur;                                                   \
        const int ccnt = cur_end - cur_start;                                   \
        ull inv2 = pack2(1.0f / (float)max(ccnt, 1));                           \
        *(ull*)&s_pool[cseg * IN_DIM + 2 * tid] = mul2(acc0, inv2);             \
        if (hasB)                                                               \
            *(ull*)&s_pool[cseg * IN_DIM + 2 * (128 + tid)] = mul2(acc1, inv2); \
        acc0 = 0ull; acc1 = 0ull;                                               \
        cur++;                                                                  \
        cur_start = cur_end;                                                    \
        cur_end = (cur < TILE_B) ? (s_bnd[cur + 1] - lo0) : 0x7fffffff;         \
    } while (0)

    // issue chunk c into stage st (tid 0 only)
    #define ISSUE(c_, mb_, st_) do {                                            \
        uint32_t off = (uint32_t)(c_) * CHUNK_BYTES;                            \
        uint32_t bytes = min((uint32_t)CHUNK_BYTES, total_bytes - off);         \
        mbar_expect_tx((mb_), bytes);                                           \
        bulk_g2s(dma_u32 + (st_) * CHUNK_BYTES, gsrc + off, bytes, (mb_));      \
    } while (0)

    // consume chunk c from stage st (all threads)
    #define CONSUME(c_, st_) do {                                               \
        const char* buf = s_dma + (st_) * CHUNK_BYTES;                          \
        const int r0 = (c_) * CHUNK_ROWS;                                       \
        const int rows = min(CHUNK_ROWS, total_rows - r0);                      \
        _Pragma("unroll")                                                       \
        for (int r = 0; r < CHUNK_ROWS; ++r) {                                  \
            if (r >= rows) break;                                               \
            const int gr = r0 + r;                                              \
            while (gr == cur_end) FLUSH();                                      \
            acc0 = add2(acc0, *(const ull*)(buf + r * ROW_BYTES + tid * 8));    \
            if (hasB)                                                           \
                acc1 = add2(acc1,                                               \
                    *(const ull*)(buf + r * ROW_BYTES + (128 + tid) * 8));      \
        }                                                                       \
    } while (0)

    // prologue: fill the ring
    if (tid == 0) {
        if (0 < nch) ISSUE(0, mb0, 0);
        if (1 < nch) ISSUE(1, mb1, 1);
        if (2 < nch) ISSUE(2, mb2, 2);
    }

    for (int cg = 0; cg < nch; cg += NSTAGE) {
        // stage 0
        {
            mbar_wait(mb0, ph0); ph0 ^= 1;
            CONSUME(cg, 0);
            __syncthreads();
            if (tid == 0 && cg + NSTAGE < nch) ISSUE(cg + NSTAGE, mb0, 0);
        }
        // stage 1
        if (cg + 1 < nch) {
            mbar_wait(mb1, ph1); ph1 ^= 1;
            CONSUME(cg + 1, 1);
            __syncthreads();
            if (tid == 0 && cg + 1 + NSTAGE < nch) ISSUE(cg + 1 + NSTAGE, mb1, 1);
        }
        // stage 2
        if (cg + 2 < nch) {
            mbar_wait(mb2, ph2); ph2 ^= 1;
            CONSUME(cg + 2, 2);
            __syncthreads();
            if (tid == 0 && cg + 2 + NSTAGE < nch) ISSUE(cg + 2 + NSTAGE, mb2, 2);
        }
    }
    while (cur < TILE_B) FLUSH();                // tail (incl. trailing empties)
    #undef FLUSH
    #undef ISSUE
    #undef CONSUME
    __syncthreads();

    // ht overlays the dma ring (streaming complete)
    float* s_ht = (float*)s_dma;   // [b][j], 4096 B

    // ---------------- Phase 2: GEMM1 (j-packed f32x2) ----------------
    const int jq = tid & 31;
    const int p  = tid >> 5;

    ull a00, a01, a10, a11;
    {
        ulonglong2 bi = *(const ulonglong2*)&b1[t * HID + 4 * jq];
        a00 = bi.x; a01 = bi.x; a10 = bi.y; a11 = bi.y;
    }
    {
        const float* w1p = W1 + (size_t)t * IN_DIM * HID + 4 * jq;
        const float* r0 = &s_pool[(2 * p) * IN_DIM];
        const float* r1 = &s_pool[(2 * p + 1) * IN_DIM];

        ulonglong2 wc[4], wn[4];
        #pragma unroll
        for (int q = 0; q < 4; ++q)
            wc[q] = *(const ulonglong2*)(w1p + q * HID);

        for (int kg = 0; kg < IN_DIM / 4; ++kg) {
            const int kb = kg * 4;
            if (kg + 1 < IN_DIM / 4) {
                const float* wq = w1p + (kb + 4) * HID;
                #pragma unroll
                for (int q = 0; q < 4; ++q)
                    wn[q] = *(const ulonglong2*)(wq + q * HID);
            }
            #pragma unroll
            for (int q = 0; q < 4; ++q) {
                ull sv0 = pack2(r0[kb + q]);
                ull sv1 = pack2(r1[kb + q]);
                a00 = fma2(wc[q].x, sv0, a00);
                a01 = fma2(wc[q].x, sv1, a01);
                a10 = fma2(wc[q].y, sv0, a10);
                a11 = fma2(wc[q].y, sv1, a11);
            }
            #pragma unroll
            for (int q = 0; q < 4; ++q) wc[q] = wn[q];
        }
    }

    *(ulonglong2*)&s_ht[(2 * p) * HID + 4 * jq] =
        make_ulonglong2(relu2(a00), relu2(a10));
    *(ulonglong2*)&s_ht[(2 * p + 1) * HID + 4 * jq] =
        make_ulonglong2(relu2(a01), relu2(a11));
    __syncthreads();

    // ---------------- Phase 3: GEMM2 (packed over j-pairs) ----------------
    const int o  = tid & 63;
    const int rh = tid >> 6;               // rows rh*4 .. rh*4+3

    ull c0 = 0ull, c1 = 0ull, c2 = 0ull, c3 = 0ull;
    {
        const float* w2p = W2 + (size_t)t * HID * OUT_DIM + o;
        float wlo[4], whi[4], nlo[4], nhi[4];
        #pragma unroll
        for (int q = 0; q < 4; ++q) {
            wlo[q] = w2p[(2 * q) * OUT_DIM];
            whi[q] = w2p[(2 * q + 1) * OUT_DIM];
        }
        for (int jg = 0; jg < 16; ++jg) {      // 64 j-pairs / 4
            const int jb = jg * 4;
            if (jg + 1 < 16) {
                #pragma unroll
                for (int q = 0; q < 4; ++q) {
                    nlo[q] = w2p[(2 * (jb + 4 + q)) * OUT_DIM];
                    nhi[q] = w2p[(2 * (jb + 4 + q) + 1) * OUT_DIM];
                }
            }
            #pragma unroll
            for (int q = 0; q < 4; ++q) {
                const int jp = jb + q;
                ull wp = packab(wlo[q], whi[q]);
                c0 = fma2(wp, *(const ull*)&s_ht[(rh * 4 + 0) * HID + 2 * jp], c0);
                c1 = fma2(wp, *(const ull*)&s_ht[(rh * 4 + 1) * HID + 2 * jp], c1);
                c2 = fma2(wp, *(const ull*)&s_ht[(rh * 4 + 2) * HID + 2 * jp], c2);
                c3 = fma2(wp, *(const ull*)&s_ht[(rh * 4 + 3) * HID + 2 * jp], c3);
            }
            #pragma unroll
            for (int q = 0; q < 4; ++q) { wlo[q] = nlo[q]; whi[q] = nhi[q]; }
        }
    }

    {
        const float bo = b2[t * OUT_DIM + o];
        float lo2, hi2;
        unpack2(c0, lo2, hi2);
        out[((size_t)(b0 + rh * 4 + 0) * T_TYPES + t) * OUT_DIM + o] = lo2 + hi2 + bo;
        unpack2(c1, lo2, hi2);
        out[((size_t)(b0 + rh * 4 + 1) * T_TYPES + t) * OUT_DIM + o] = lo2 + hi2 + bo;
        unpack2(c2, lo2, hi2);
        out[((size_t)(b0 + rh * 4 + 2) * T_TYPES + t) * OUT_DIM + o] = lo2 + hi2 + bo;
        unpack2(c3, lo2, hi2);
        out[((size_t)(b0 + rh * 4 + 3) * T_TYPES + t) * OUT_DIM + o] = lo2 + hi2 + bo;
    }
}

// ---------------------------------------------------------------------------
extern "C" void kernel_launch(void* const* d_in, const int* in_sizes, int n_in,
                              void* d_out, int out_size) {
    const float* feat = (const float*)d_in[0];
    const int*   seg  = (const int*)d_in[1];
    const float* W1   = (const float*)d_in[2];
    const float* b1   = (const float*)d_in[3];
    const float* W2   = (const float*)d_in[4];
    const float* b2   = (const float*)d_in[5];
    float* out = (float*)d_out;

    bounds_kernel<<<T_TYPES, B_BATCH>>>(seg);

    dim3 grid(N_TILES, T_TYPES);
    fused_kernel<<<grid, 128>>>(feat, W1, b1, W2, b2, out);
}

// round 15
// speedup vs baseline: 1.3458x; 1.0528x over previous
#include <cuda_runtime.h>
#include <cuda_bf16.h>
#include <cstdint>

// Problem constants
#define T_TYPES 27
#define N_NODES 16384
#define B_BATCH 256
#define IN_DIM  300
#define HID     128
#define OUT_DIM 64
#define TILE_B  8
#define N_TILES (B_BATCH / TILE_B)     // 32
#define ROW_BYTES 1200                 // 300 floats
#define CHUNK_ROWS 8
#define CHUNK_BYTES (CHUNK_ROWS * ROW_BYTES)   // 9600
#define ROW_ULL 150                    // 300 floats = 150 f32x2

__device__ int g_bounds[T_TYPES * (B_BATCH + 1)];

typedef unsigned long long ull;

__device__ __forceinline__ ull fma2(ull a, ull b, ull c) {
    ull d;
    asm("fma.rn.f32x2 %0, %1, %2, %3;" : "=l"(d) : "l"(a), "l"(b), "l"(c));
    return d;
}
__device__ __forceinline__ ull add2(ull a, ull b) {
    ull d;
    asm("add.rn.f32x2 %0, %1, %2;" : "=l"(d) : "l"(a), "l"(b));
    return d;
}
__device__ __forceinline__ ull mul2(ull a, ull b) {
    ull d;
    asm("mul.rn.f32x2 %0, %1, %2;" : "=l"(d) : "l"(a), "l"(b));
    return d;
}
__device__ __forceinline__ ull pack2(float x) {
    ull d; asm("mov.b64 %0, {%1, %1};" : "=l"(d) : "f"(x)); return d;
}
__device__ __forceinline__ ull packab(float a, float b) {
    ull d; asm("mov.b64 %0, {%1, %2};" : "=l"(d) : "f"(a), "f"(b)); return d;
}
__device__ __forceinline__ void unpack2(ull v, float& lo, float& hi) {
    asm("mov.b64 {%0, %1}, %2;" : "=f"(lo), "=f"(hi) : "l"(v));
}
__device__ __forceinline__ ull relu2(ull v) {
    float lo, hi; unpack2(v, lo, hi);
    return packab(fmaxf(lo, 0.f), fmaxf(hi, 0.f));
}

__device__ __forceinline__ uint32_t s2u(const void* p) {
    uint32_t a;
    asm("{ .reg .u64 t; cvta.to.shared.u64 t, %1; cvt.u32.u64 %0, t; }"
        : "=r"(a) : "l"(p));
    return a;
}
__device__ __forceinline__ void mbar_init(uint32_t m, uint32_t cnt) {
    asm volatile("mbarrier.init.shared.b64 [%0], %1;" :: "r"(m), "r"(cnt) : "memory");
}
__device__ __forceinline__ void mbar_expect_tx(uint32_t m, uint32_t bytes) {
    asm volatile("mbarrier.arrive.expect_tx.shared.b64 _, [%0], %1;"
                 :: "r"(m), "r"(bytes) : "memory");
}
__device__ __forceinline__ ull mk_evict_first_policy() {
    ull pol;
    asm("createpolicy.fractional.L2::evict_first.b64 %0, 1.0;" : "=l"(pol));
    return pol;
}
__device__ __forceinline__ void bulk_g2s(uint32_t dst, const void* src,
                                         uint32_t bytes, uint32_t m, ull pol) {
    asm volatile(
        "cp.async.bulk.shared::cta.global.mbarrier::complete_tx::bytes.L2::cache_hint "
        "[%0], [%1], %2, [%3], %4;"
        :: "r"(dst), "l"(src), "r"(bytes), "r"(m), "l"(pol) : "memory");
}
__device__ __forceinline__ void mbar_wait(uint32_t m, int parity) {
    asm volatile(
        "{\n\t"
        ".reg .pred P;\n\t"
        "WAIT_%=:\n\t"
        "mbarrier.try_wait.parity.acquire.cta.shared::cta.b64 P, [%0], %1;\n\t"
        "@!P bra WAIT_%=;\n\t"
        "}" :: "r"(m), "r"(parity) : "memory");
}

// ---------------------------------------------------------------------------
// Kernel 0: segment bounds via histogram + scan. grid=27, block=256.
// int4-vectorized loads for 4x memory-level parallelism.
// ---------------------------------------------------------------------------
__global__ void bounds_kernel(const int* __restrict__ seg) {
    const int t = blockIdx.x;
    const int tid = threadIdx.x;
    __shared__ int hist[B_BATCH];

    hist[tid] = 0;
    __syncthreads();
    const int4* s4 = (const int4*)(seg + (size_t)t * N_NODES);
    #pragma unroll 4
    for (int i = tid; i < N_NODES / 4; i += B_BATCH) {
        int4 v = s4[i];
        atomicAdd(&hist[v.x], 1);
        atomicAdd(&hist[v.y], 1);
        atomicAdd(&hist[v.z], 1);
        atomicAdd(&hist[v.w], 1);
    }
    __syncthreads();

    for (int off = 1; off < B_BATCH; off <<= 1) {
        int u = (tid >= off) ? hist[tid - off] : 0;
        __syncthreads();
        hist[tid] += u;
        __syncthreads();
    }
    if (tid == 0) g_bounds[t * (B_BATCH + 1)] = 0;
    g_bounds[t * (B_BATCH + 1) + tid + 1] = hist[tid];
}

// ---------------------------------------------------------------------------
// Fused kernel: grid=(32, 27) = 864 blocks (single wave @6/SM), 128 threads.
// Phase 1: 2-stage cp.async.bulk double buffer (R12 config, measured best),
//          evict-first L2 policy; f32x2 accumulators; in-order segment flush.
// Phase 2: 2-layer MLP from smem (ht overlays the dma ring).
// ---------------------------------------------------------------------------
__global__ __launch_bounds__(128, 6)
void fused_kernel(const float* __restrict__ feat,
                  const float* __restrict__ W1,
                  const float* __restrict__ b1,
                  const float* __restrict__ W2,
                  const float* __restrict__ b2,
                  float* __restrict__ out) {
    const int t   = blockIdx.y;
    const int b0  = blockIdx.x * TILE_B;
    const int tid = threadIdx.x;

    __shared__ __align__(128) char  s_dma[2 * CHUNK_BYTES];   // 19200 B
    __shared__ __align__(16)  float s_pool[TILE_B * IN_DIM];  //  9600 B [b][k]
    __shared__ __align__(8)   ull   s_mbar[2];
    __shared__ int s_bnd[TILE_B + 1];

    if (tid < TILE_B + 1)
        s_bnd[tid] = g_bounds[t * (B_BATCH + 1) + b0 + tid];
    if (tid == 0) {
        mbar_init(s2u(&s_mbar[0]), 1);
        mbar_init(s2u(&s_mbar[1]), 1);
    }
    __syncthreads();

    const int lo0 = s_bnd[0];
    const int total_rows = s_bnd[TILE_B] - lo0;
    const uint32_t total_bytes = (uint32_t)total_rows * ROW_BYTES;
    const int nch = (int)((total_bytes + CHUNK_BYTES - 1) / CHUNK_BYTES);

    const uint32_t dma_u32 = s2u(s_dma);
    const uint32_t mb0 = s2u(&s_mbar[0]);
    const uint32_t mb1 = s2u(&s_mbar[1]);
    const char* gsrc = (const char*)(feat + ((size_t)t * N_NODES + lo0) * IN_DIM);
    const ull pol = mk_evict_first_policy();

    // ---------------- Phase 1: TMA-bulk streaming + segmented reduce ----------
    ull acc0 = 0ull, acc1 = 0ull;
    const bool hasB = tid < (ROW_ULL - 128);   // tid < 22 owns a 2nd column
    int cur = 0;
    int cur_start = 0;
    int cur_end = s_bnd[1] - lo0;
    int ph0 = 0, ph1 = 0;

    #define FLUSH() do {                                                        \
        const int cseg = cur;                                                   \
        const int ccnt = cur_end - cur_start;                                   \
        ull inv2 = pack2(1.0f / (float)max(ccnt, 1));                           \
        *(ull*)&s_pool[cseg * IN_DIM + 2 * tid] = mul2(acc0, inv2);             \
        if (hasB)                                                               \
            *(ull*)&s_pool[cseg * IN_DIM + 2 * (128 + tid)] = mul2(acc1, inv2); \
        acc0 = 0ull; acc1 = 0ull;                                               \
        cur++;                                                                  \
        cur_start = cur_end;                                                    \
        cur_end = (cur < TILE_B) ? (s_bnd[cur + 1] - lo0) : 0x7fffffff;         \
    } while (0)

    if (nch > 0 && tid == 0) {
        uint32_t bytes = min((uint32_t)CHUNK_BYTES, total_bytes);
        mbar_expect_tx(mb0, bytes);
        bulk_g2s(dma_u32, gsrc, bytes, mb0, pol);
    }

    for (int c = 0; c < nch; ++c) {
        if (tid == 0 && c + 1 < nch) {
            uint32_t off = (uint32_t)(c + 1) * CHUNK_BYTES;
            uint32_t bytes = min((uint32_t)CHUNK_BYTES, total_bytes - off);
            uint32_t m = ((c + 1) & 1) ? mb1 : mb0;
            mbar_expect_tx(m, bytes);
            bulk_g2s(dma_u32 + ((c + 1) & 1) * CHUNK_BYTES, gsrc + off, bytes, m, pol);
        }
        if (c & 1) { mbar_wait(mb1, ph1); ph1 ^= 1; }
        else       { mbar_wait(mb0, ph0); ph0 ^= 1; }

        const char* buf = s_dma + (c & 1) * CHUNK_BYTES;
        const int r0 = c * CHUNK_ROWS;
        const int rows = min(CHUNK_ROWS, total_rows - r0);
        #pragma unroll
        for (int r = 0; r < CHUNK_ROWS; ++r) {
            if (r >= rows) break;
            const int gr = r0 + r;
            while (gr == cur_end) FLUSH();       // uniform across threads
            acc0 = add2(acc0, *(const ull*)(buf + r * ROW_BYTES + tid * 8));
            if (hasB)
                acc1 = add2(acc1, *(const ull*)(buf + r * ROW_BYTES + (128 + tid) * 8));
        }
        __syncthreads();   // all threads done reading buf (c&1) before reuse
    }
    while (cur < TILE_B) FLUSH();                // tail (incl. trailing empties)
    #undef FLUSH
    __syncthreads();

    // ht overlays the dma ring (streaming complete)
    float* s_ht = (float*)s_dma;   // [b][j], 4096 B

    // ---------------- Phase 2: GEMM1 (j-packed f32x2) ----------------
    const int jq = tid & 31;
    const int p  = tid >> 5;

    ull a00, a01, a10, a11;
    {
        ulonglong2 bi = *(const ulonglong2*)&b1[t * HID + 4 * jq];
        a00 = bi.x; a01 = bi.x; a10 = bi.y; a11 = bi.y;
    }
    {
        const float* w1p = W1 + (size_t)t * IN_DIM * HID + 4 * jq;
        const float* r0 = &s_pool[(2 * p) * IN_DIM];
        const float* r1 = &s_pool[(2 * p + 1) * IN_DIM];

        ulonglong2 wc[4], wn[4];
        #pragma unroll
        for (int q = 0; q < 4; ++q)
            wc[q] = *(const ulonglong2*)(w1p + q * HID);

        for (int kg = 0; kg < IN_DIM / 4; ++kg) {
            const int kb = kg * 4;
            if (kg + 1 < IN_DIM / 4) {
                const float* wq = w1p + (kb + 4) * HID;
                #pragma unroll
                for (int q = 0; q < 4; ++q)
                    wn[q] = *(const ulonglong2*)(wq + q * HID);
            }
            #pragma unroll
            for (int q = 0; q < 4; ++q) {
                ull sv0 = pack2(r0[kb + q]);
                ull sv1 = pack2(r1[kb + q]);
                a00 = fma2(wc[q].x, sv0, a00);
                a01 = fma2(wc[q].x, sv1, a01);
                a10 = fma2(wc[q].y, sv0, a10);
                a11 = fma2(wc[q].y, sv1, a11);
            }
            #pragma unroll
            for (int q = 0; q < 4; ++q) wc[q] = wn[q];
        }
    }

    *(ulonglong2*)&s_ht[(2 * p) * HID + 4 * jq] =
        make_ulonglong2(relu2(a00), relu2(a10));
    *(ulonglong2*)&s_ht[(2 * p + 1) * HID + 4 * jq] =
        make_ulonglong2(relu2(a01), relu2(a11));
    __syncthreads();

    // ---------------- Phase 3: GEMM2 (packed over j-pairs) ----------------
    const int o  = tid & 63;
    const int rh = tid >> 6;               // rows rh*4 .. rh*4+3

    ull c0 = 0ull, c1 = 0ull, c2 = 0ull, c3 = 0ull;
    {
        const float* w2p = W2 + (size_t)t * HID * OUT_DIM + o;
        float wlo[4], whi[4], nlo[4], nhi[4];
        #pragma unroll
        for (int q = 0; q < 4; ++q) {
            wlo[q] = w2p[(2 * q) * OUT_DIM];
            whi[q] = w2p[(2 * q + 1) * OUT_DIM];
        }
        for (int jg = 0; jg < 16; ++jg) {      // 64 j-pairs / 4
            const int jb = jg * 4;
            if (jg + 1 < 16) {
                #pragma unroll
                for (int q = 0; q < 4; ++q) {
                    nlo[q] = w2p[(2 * (jb + 4 + q)) * OUT_DIM];
                    nhi[q] = w2p[(2 * (jb + 4 + q) + 1) * OUT_DIM];
                }
            }
            #pragma unroll
            for (int q = 0; q < 4; ++q) {
                const int jp = jb + q;
                ull wp = packab(wlo[q], whi[q]);
                c0 = fma2(wp, *(const ull*)&s_ht[(rh * 4 + 0) * HID + 2 * jp], c0);
                c1 = fma2(wp, *(const ull*)&s_ht[(rh * 4 + 1) * HID + 2 * jp], c1);
                c2 = fma2(wp, *(const ull*)&s_ht[(rh * 4 + 2) * HID + 2 * jp], c2);
                c3 = fma2(wp, *(const ull*)&s_ht[(rh * 4 + 3) * HID + 2 * jp], c3);
            }
            #pragma unroll
            for (int q = 0; q < 4; ++q) { wlo[q] = nlo[q]; whi[q] = nhi[q]; }
        }
    }

    {
        const float bo = b2[t * OUT_DIM + o];
        float lo2, hi2;
        unpack2(c0, lo2, hi2);
        out[((size_t)(b0 + rh * 4 + 0) * T_TYPES + t) * OUT_DIM + o] = lo2 + hi2 + bo;
        unpack2(c1, lo2, hi2);
        out[((size_t)(b0 + rh * 4 + 1) * T_TYPES + t) * OUT_DIM + o] = lo2 + hi2 + bo;
        unpack2(c2, lo2, hi2);
        out[((size_t)(b0 + rh * 4 + 2) * T_TYPES + t) * OUT_DIM + o] = lo2 + hi2 + bo;
        unpack2(c3, lo2, hi2);
        out[((size_t)(b0 + rh * 4 + 3) * T_TYPES + t) * OUT_DIM + o] = lo2 + hi2 + bo;
    }
}

// ---------------------------------------------------------------------------
extern "C" void kernel_launch(void* const* d_in, const int* in_sizes, int n_in,
                              void* d_out, int out_size) {
    const float* feat = (const float*)d_in[0];
    const int*   seg  = (const int*)d_in[1];
    const float* W1   = (const float*)d_in[2];
    const float* b1   = (const float*)d_in[3];
    const float* W2   = (const float*)d_in[4];
    const float* b2   = (const float*)d_in[5];
    float* out = (float*)d_out;

    bounds_kernel<<<T_TYPES, B_BATCH>>>(seg);

    dim3 grid(N_TILES, T_TYPES);
    fused_kernel<<<grid, 128>>>(feat, W1, b1, W2, b2, out);
}